// round 12
// baseline (speedup 1.0000x reference)
#include <cuda_runtime.h>
#include <cuda_fp16.h>
#include <mma.h>
#include <math.h>
#include <stdint.h>

using namespace nvcuda;

// ---------------- problem constants ----------------
#define BB 32
#define SS 197
#define EE 768
#define HH 12
#define DHH 64
#define FF_ 2048
#define LL 4
#define CC 1000
#define BS (BB * SS)     // 6304
#define SP2 256          // padded key length inside fused attention
#define NQKV 2304        // 3 * H * DH packed output width
#define LN_EPS 1e-5f

// ---------------- scratch (device globals; allocation-free rule) ------------
__device__ float  g_h    [BS * EE];
__device__ float  g_res1 [BS * EE];
__device__ __half g_xnh  [BS * EE];
__device__ __half g_qkvh [(BS + 32) * NQKV];
__device__ __half g_oh   [BS * EE];
__device__ __half g_ffh  [BS * FF_];
// fp16 weights (converted once per launch)
__device__ __half g_wqkv [LL * EE * NQKV];
__device__ __half g_wcv  [LL * EE * EE];
__device__ __half g_w1   [LL * EE * FF_];
__device__ __half g_w2   [LL * FF_ * EE];

// ---------------- cp.async helpers ------------------------------------------
__device__ __forceinline__ void cp_async16(void* smem_dst, const void* gsrc,
                                           bool pred) {
    unsigned int s = (unsigned int)__cvta_generic_to_shared(smem_dst);
    int sz = pred ? 16 : 0;
    asm volatile("cp.async.cg.shared.global [%0], [%1], 16, %2;\n"
                 :: "r"(s), "l"(gsrc), "r"(sz));
}
__device__ __forceinline__ void cp_commit() {
    asm volatile("cp.async.commit_group;\n" ::: "memory");
}
template <int N>
__device__ __forceinline__ void cp_wait() {
    asm volatile("cp.async.wait_group %0;\n" :: "n"(N) : "memory");
}

// ---------------- weight conversion (vectorized: 8 elems/thread) ------------
__global__ void cvt_f2h_kernel(const float* __restrict__ src,
                               __half* __restrict__ dst, int n8) {
    int i = blockIdx.x * 256 + threadIdx.x;
    if (i >= n8) return;
    long long o = (long long)i * 8;
    float4 v0 = *reinterpret_cast<const float4*>(src + o);
    float4 v1 = *reinterpret_cast<const float4*>(src + o + 4);
    __half2 h[4];
    h[0] = __floats2half2_rn(v0.x, v0.y);
    h[1] = __floats2half2_rn(v0.z, v0.w);
    h[2] = __floats2half2_rn(v1.x, v1.y);
    h[3] = __floats2half2_rn(v1.z, v1.w);
    *reinterpret_cast<uint4*>(dst + o) = *reinterpret_cast<uint4*>(h);
}

__global__ void pack_qkv_kernel(const float* __restrict__ Wq,
                                const float* __restrict__ Wk,
                                const float* __restrict__ Wv,
                                __half* __restrict__ dst) {
    const long long per = (long long)LL * HH * EE * DHH;   // 2359296
    long long i8 = ((long long)blockIdx.x * 256 + threadIdx.x) * 8;
    if (i8 >= 3 * per) return;
    int mat = (int)(i8 / per);
    long long r = i8 % per;
    int d = (int)(r % DHH);                  // multiple of 8
    int e = (int)((r / DHH) % EE);
    int h = (int)((r / (DHH * EE)) % HH);
    int l = (int)(r / ((long long)DHH * EE * HH));
    const float* src = (mat == 0) ? Wq : (mat == 1) ? Wk : Wv;
    float4 v0 = *reinterpret_cast<const float4*>(src + r);
    float4 v1 = *reinterpret_cast<const float4*>(src + r + 4);
    __half2 hh[4];
    hh[0] = __floats2half2_rn(v0.x, v0.y);
    hh[1] = __floats2half2_rn(v0.z, v0.w);
    hh[2] = __floats2half2_rn(v1.x, v1.y);
    hh[3] = __floats2half2_rn(v1.z, v1.w);
    *reinterpret_cast<uint4*>(
        dst + ((long long)l * EE + e) * NQKV + mat * 768 + h * 64 + d) =
        *reinterpret_cast<uint4*>(hh);
}

// ---------------- layernorm: warp per row (shuffle-only), fp16 out ----------
__global__ __launch_bounds__(256)
void layernorm_kernel(const float* __restrict__ x,
                      const float* __restrict__ w,
                      const float* __restrict__ b,
                      __half* __restrict__ out) {
    int wid = threadIdx.x >> 5, lane = threadIdx.x & 31;
    int row = blockIdx.x * 8 + wid;
    if (row >= BS) return;
    const float* xr = x + (long long)row * EE;
    __half* orow = out + (long long)row * EE;

    float v[24];
    float s = 0.f, s2 = 0.f;
    #pragma unroll
    for (int j = 0; j < 24; j++) {
        v[j] = xr[lane + j * 32];
        s += v[j]; s2 += v[j] * v[j];
    }
    #pragma unroll
    for (int off = 16; off > 0; off >>= 1) {
        s  += __shfl_xor_sync(0xffffffffu, s, off);
        s2 += __shfl_xor_sync(0xffffffffu, s2, off);
    }
    float mu = s * (1.f / EE);
    float var = s2 * (1.f / EE) - mu * mu;
    float rstd = rsqrtf(var + LN_EPS);
    #pragma unroll
    for (int j = 0; j < 24; j++) {
        int i = lane + j * 32;
        orow[i] = __float2half_rn((v[j] - mu) * rstd * w[i] + b[i]);
    }
}

// ---------------- fused flash attention -------------------------------------
// One block per (q-tile of 64, b*h). All intermediates in smem.
#define LDQ 72
#define LDK 72
#define LDP 264
#define LDSF 260
#define LDV 72
#define LDSO 68
#define SM_Q 0
#define SM_K 9216                      // 64*LDQ*2
#define SM_SF (SM_K + SP2 * LDK * 2)   // 46080
#define SM_OS (SM_SF + 40960)
#define ATTN_SMEM (SM_SF + 64 * LDSF * 4)   // 112640 B

__global__ __launch_bounds__(256)
void fused_attn_kernel(const __half* __restrict__ qkv,
                       __half* __restrict__ o, float inv_scale) {
    extern __shared__ char sm[];
    __half* Qs = reinterpret_cast<__half*>(sm + SM_Q);
    __half* Ks = reinterpret_cast<__half*>(sm + SM_K);
    __half* Ph = Ks;
    float*  Sf = reinterpret_cast<float*>(sm + SM_SF);
    __half* Vs = reinterpret_cast<__half*>(sm + SM_SF);
    float*  Os = reinterpret_cast<float*>(sm + SM_OS);

    int qt = blockIdx.x;
    int bh = blockIdx.y;
    int b = bh / HH, h = bh % HH;
    const __half* base = qkv + (long long)b * SS * NQKV + h * 64;
    int q0 = qt * 64;

    int tid = threadIdx.x;
    int wid = tid >> 5, lane = tid & 31;
    const uint4 z4 = {0u, 0u, 0u, 0u};

    #pragma unroll
    for (int e = 0; e < 2; e++) {
        int i = tid + e * 256;
        int r = i >> 3, c = (i & 7) * 8;
        int gq = q0 + r;
        uint4 v = (gq < SS)
            ? *reinterpret_cast<const uint4*>(base + (long long)gq * NQKV + c)
            : z4;
        *reinterpret_cast<uint4*>(&Qs[r * LDQ + c]) = v;
    }
    #pragma unroll
    for (int e = 0; e < 8; e++) {
        int i = tid + e * 256;
        int r = i >> 3, c = (i & 7) * 8;
        uint4 v = (r < SS)
            ? *reinterpret_cast<const uint4*>(base + 768 +
                                              (long long)r * NQKV + c)
            : z4;
        *reinterpret_cast<uint4*>(&Ks[r * LDK + c]) = v;
    }
    __syncthreads();

    {
        wmma::fragment<wmma::accumulator, 16, 16, 16, float> acc[4][2];
        #pragma unroll
        for (int i = 0; i < 4; i++)
            #pragma unroll
            for (int j = 0; j < 2; j++)
                wmma::fill_fragment(acc[i][j], 0.f);
        #pragma unroll
        for (int kt = 0; kt < 4; kt++) {
            wmma::fragment<wmma::matrix_a, 16, 16, 16, __half,
                           wmma::row_major> af[4];
            wmma::fragment<wmma::matrix_b, 16, 16, 16, __half,
                           wmma::col_major> bf[2];
            #pragma unroll
            for (int i = 0; i < 4; i++)
                wmma::load_matrix_sync(af[i],
                    Qs + (i * 16) * LDQ + kt * 16, LDQ);
            #pragma unroll
            for (int j = 0; j < 2; j++)
                wmma::load_matrix_sync(bf[j],
                    Ks + (wid * 32 + j * 16) * LDK + kt * 16, LDK);
            #pragma unroll
            for (int i = 0; i < 4; i++)
                #pragma unroll
                for (int j = 0; j < 2; j++)
                    wmma::mma_sync(acc[i][j], af[i], bf[j], acc[i][j]);
        }
        #pragma unroll
        for (int i = 0; i < 4; i++)
            #pragma unroll
            for (int j = 0; j < 2; j++)
                wmma::store_matrix_sync(
                    Sf + (i * 16) * LDSF + wid * 32 + j * 16, acc[i][j],
                    LDSF, wmma::mem_row_major);
    }
    __syncthreads();

    #pragma unroll
    for (int rr = 0; rr < 8; rr++) {
        int r = wid * 8 + rr;
        float m = -1e30f;
        for (int c = lane; c < SS; c += 32)
            m = fmaxf(m, Sf[r * LDSF + c] * inv_scale);
        #pragma unroll
        for (int off = 16; off > 0; off >>= 1)
            m = fmaxf(m, __shfl_xor_sync(0xffffffffu, m, off));
        float sum = 0.f;
        for (int c = lane; c < SS; c += 32) {
            float e = expf(Sf[r * LDSF + c] * inv_scale - m);
            Sf[r * LDSF + c] = e;
            sum += e;
        }
        #pragma unroll
        for (int off = 16; off > 0; off >>= 1)
            sum += __shfl_xor_sync(0xffffffffu, sum, off);
        float inv = 1.f / sum;
        for (int c = lane; c < SP2; c += 32)
            Ph[r * LDP + c] = (c < SS)
                ? __float2half_rn(Sf[r * LDSF + c] * inv) : __half(0.f);
    }
    __syncthreads();

    #pragma unroll
    for (int e = 0; e < 8; e++) {
        int i = tid + e * 256;
        int r = i >> 3, c = (i & 7) * 8;
        uint4 v = (r < SS)
            ? *reinterpret_cast<const uint4*>(base + 1536 +
                                              (long long)r * NQKV + c)
            : z4;
        *reinterpret_cast<uint4*>(&Vs[r * LDV + c]) = v;
    }
    __syncthreads();

    {
        int wm = wid >> 1, wn = wid & 1;
        wmma::fragment<wmma::accumulator, 16, 16, 16, float> acc[2];
        wmma::fill_fragment(acc[0], 0.f);
        wmma::fill_fragment(acc[1], 0.f);
        #pragma unroll
        for (int kt = 0; kt < SP2 / 16; kt++) {
            wmma::fragment<wmma::matrix_a, 16, 16, 16, __half,
                           wmma::row_major> af;
            wmma::fragment<wmma::matrix_b, 16, 16, 16, __half,
                           wmma::row_major> bf[2];
            wmma::load_matrix_sync(af, Ph + (wm * 16) * LDP + kt * 16, LDP);
            #pragma unroll
            for (int j = 0; j < 2; j++)
                wmma::load_matrix_sync(bf[j],
                    Vs + (kt * 16) * LDV + wn * 32 + j * 16, LDV);
            #pragma unroll
            for (int j = 0; j < 2; j++)
                wmma::mma_sync(acc[j], af, bf[j], acc[j]);
        }
        #pragma unroll
        for (int j = 0; j < 2; j++)
            wmma::store_matrix_sync(
                Os + (wm * 16) * LDSO + wn * 32 + j * 16, acc[j],
                LDSO, wmma::mem_row_major);
    }
    __syncthreads();

    #pragma unroll
    for (int e = 0; e < 16; e++) {
        int i = tid + e * 256;
        int m = i >> 6, d = i & 63;
        int gq = q0 + m;
        if (gq < SS)
            o[((long long)b * SS + gq) * EE + h * 64 + d] =
                __float2half_rn(Os[m * LDSO + d]);
    }
}

// ---------------- FP16 TC GEMM: 128x256 tile, 64x64 warp tiles, BK=32 -------
// 3-stage cp.async pipeline. Requires K % 32 == 0, N % 256 == 0, rows 16B
// aligned. Only M may be ragged.
// EPI: 0: C=acc  1: C=gelu(acc+bias)  2: C=acc+D  3: C=acc+bias+D
#define HG_LDA 40
#define HG_LDB 264
#define HG_STAGE_HALFS (128 * HG_LDA + 32 * HG_LDB)   // 13568
#define HG_SMEM (3 * HG_STAGE_HALFS * 2)              // 81408 (> epi 34816)

template <int EPI, bool OUTH>
__global__ __launch_bounds__(256)
void hgemm_kernel(const __half* __restrict__ A, const __half* __restrict__ Bm,
                  void* __restrict__ Cv,
                  const float* __restrict__ bias, const float* __restrict__ Dm,
                  int M, int N, int K, int lda, int ldb, int ldc) {
    constexpr int BM = 128, BK = 32;
    constexpr int WARP_M = 64, WARP_N = 64;
    constexpr int AF = 4, BF = 4;
    constexpr int LDA_H = HG_LDA;
    constexpr int LDB_H = HG_LDB;
    constexpr int LDST = 68;

    const int m0 = blockIdx.y * BM, n0 = blockIdx.x * 256;

    extern __shared__ __align__(16) char smem_raw[];
    float* epi = reinterpret_cast<float*>(smem_raw);

    int tid = threadIdx.x;
    int wid = tid >> 5;
    int wm = wid & 1, wn = wid >> 1;   // 2 x 4 warp grid (64m x 64n tiles)

    wmma::fragment<wmma::accumulator, 16, 16, 16, float> acc[AF][BF];
    #pragma unroll
    for (int i = 0; i < AF; i++)
        #pragma unroll
        for (int j = 0; j < BF; j++)
            wmma::fill_fragment(acc[i][j], 0.f);

    // per-thread fixed copy coordinates
    const int am = tid >> 2, ak = (tid & 3) * 8;           // A: 128x32
    const int bk = tid >> 5, bn = (tid & 31) * 8;          // B rows 0..7 base
    const bool apred0 = (m0 + am < M);
    const bool apred1 = (m0 + am + 64 < M);
    const long long arow0 = (long long)(apred0 ? (m0 + am) : (M - 1)) * lda;
    const long long arow1 = (long long)(apred1 ? (m0 + am + 64) : (M - 1)) * lda;

    auto loadStage = [&](int t, int s) {
        __half* As = reinterpret_cast<__half*>(smem_raw) + s * HG_STAGE_HALFS;
        __half* Bs = As + BM * LDA_H;
        int k0 = t * BK;
        cp_async16(&As[am * LDA_H + ak], A + arow0 + k0 + ak, apred0);
        cp_async16(&As[(am + 64) * LDA_H + ak], A + arow1 + k0 + ak, apred1);
        // B: 32 x 256 halfs = 1024 vec16 -> 4 per thread (k rows +0,8,16,24)
        #pragma unroll
        for (int e = 0; e < 4; e++) {
            int k = bk + e * 8;
            cp_async16(&Bs[k * LDB_H + bn],
                       Bm + (long long)(k0 + k) * ldb + n0 + bn, true);
        }
        cp_commit();
    };

    auto compute = [&](int s) {
        const __half* As = reinterpret_cast<const __half*>(smem_raw)
                           + s * HG_STAGE_HALFS;
        const __half* Bs = As + BM * LDA_H;
        #pragma unroll
        for (int kt = 0; kt < BK / 16; kt++) {
            wmma::fragment<wmma::matrix_a, 16, 16, 16, __half,
                           wmma::row_major> af[AF];
            wmma::fragment<wmma::matrix_b, 16, 16, 16, __half,
                           wmma::row_major> bf[BF];
            #pragma unroll
            for (int i = 0; i < AF; i++)
                wmma::load_matrix_sync(
                    af[i], As + (wm * WARP_M + i * 16) * LDA_H + kt * 16,
                    LDA_H);
            #pragma unroll
            for (int j = 0; j < BF; j++)
                wmma::load_matrix_sync(
                    bf[j], Bs + (kt * 16) * LDB_H + wn * WARP_N + j * 16,
                    LDB_H);
            #pragma unroll
            for (int i = 0; i < AF; i++)
                #pragma unroll
                for (int j = 0; j < BF; j++)
                    wmma::mma_sync(acc[i][j], af[i], bf[j], acc[i][j]);
        }
    };

    // ---- 3-stage cp.async pipeline, one barrier per iter ----
    const int nk = K / BK;
    loadStage(0, 0);
    if (nk > 1) loadStage(1, 1);
    for (int t = 0; t < nk; t++) {
        if (t + 1 < nk) cp_wait<1>(); else cp_wait<0>();
        __syncthreads();
        if (t + 2 < nk) loadStage(t + 2, (t + 2) % 3);
        compute(t % 3);
    }
    __syncthreads();

    // ---- epilogue: four 64-wide column chunks staged through fp32 smem ----
    #pragma unroll
    for (int h = 0; h < 4; h++) {
        if (wn == h) {
            #pragma unroll
            for (int i = 0; i < AF; i++)
                #pragma unroll
                for (int j = 0; j < BF; j++)
                    wmma::store_matrix_sync(
                        epi + (wm * WARP_M + i * 16) * LDST + j * 16,
                        acc[i][j], LDST, wmma::mem_row_major);
        }
        __syncthreads();

        int nl = tid & 63;
        int n = n0 + h * 64 + nl;
        {
            float bn_ = (EPI == 1 || EPI == 3) ? bias[n] : 0.f;
            #pragma unroll 8
            for (int p = 0; p < 32; p++) {
                int r = (tid >> 6) + p * 4;
                int m = m0 + r;
                if (m >= M) break;
                float v = epi[r * LDST + nl];
                if (EPI == 1) {
                    v += bn_;
                    v = 0.5f * v * (1.f + erff(v * 0.70710678118654752f));
                } else if (EPI == 2) {
                    v += Dm[(long long)m * ldc + n];
                } else if (EPI == 3) {
                    v += bn_ + Dm[(long long)m * ldc + n];
                }
                if (OUTH)
                    ((__half*)Cv)[(long long)m * ldc + n] = __float2half_rn(v);
                else
                    ((float*)Cv)[(long long)m * ldc + n] = v;
            }
        }
        if (h < 3) __syncthreads();
    }
}

// ---------------- classifier + final softmax: one block per batch ------------
__global__ void classifier_kernel(const float* __restrict__ hbuf,
                                  const float* __restrict__ Wc,
                                  const float* __restrict__ bc,
                                  float* __restrict__ out) {
    int b = blockIdx.x;
    int tid = threadIdx.x;  // 256
    __shared__ float xs[EE];
    __shared__ float lg[CC];
    __shared__ float red[256];

    const float* xr = hbuf + (long long)b * SS * EE;  // row s=0
    for (int i = tid; i < EE; i += 256) xs[i] = xr[i];
    __syncthreads();

    for (int c = tid; c < CC; c += 256) {
        float acc = bc[c];
        for (int e = 0; e < EE; e++) acc += xs[e] * Wc[(long long)e * CC + c];
        lg[c] = acc;
    }
    __syncthreads();

    float m = -1e30f;
    for (int c = tid; c < CC; c += 256) m = fmaxf(m, lg[c]);
    red[tid] = m; __syncthreads();
    for (int st = 128; st > 0; st >>= 1) {
        if (tid < st) red[tid] = fmaxf(red[tid], red[tid + st]);
        __syncthreads();
    }
    m = red[0];
    __syncthreads();

    float sum = 0.f;
    for (int c = tid; c < CC; c += 256) {
        float e = expf(lg[c] - m);
        lg[c] = e; sum += e;
    }
    red[tid] = sum; __syncthreads();
    for (int st = 128; st > 0; st >>= 1) {
        if (tid < st) red[tid] += red[tid + st];
        __syncthreads();
    }
    float inv = 1.f / red[0];
    for (int c = tid; c < CC; c += 256)
        out[(long long)b * CC + c] = lg[c] * inv;
}

// ---------------- host orchestration ----------------------------------------
extern "C" void kernel_launch(void* const* d_in, const int* in_sizes, int n_in,
                              void* d_out, int out_size) {
    const float* x     = (const float*)d_in[0];
    const float* Wk    = (const float*)d_in[1];
    const float* Wq    = (const float*)d_in[2];
    const float* Wv    = (const float*)d_in[3];
    const float* Wconv = (const float*)d_in[4];
    const float* ln1_w = (const float*)d_in[5];
    const float* ln1_b = (const float*)d_in[6];
    const float* ln2_w = (const float*)d_in[7];
    const float* ln2_b = (const float*)d_in[8];
    const float* W1    = (const float*)d_in[9];
    const float* b1    = (const float*)d_in[10];
    const float* W2    = (const float*)d_in[11];
    const float* b2    = (const float*)d_in[12];
    const float* Wc    = (const float*)d_in[13];
    const float* bc    = (const float*)d_in[14];
    float* out = (float*)d_out;

    float *ph, *pres1;
    __half *pxnh, *pqkvh, *poh, *pffh, *pwqkv, *pwcv, *pw1, *pw2;
    cudaGetSymbolAddress((void**)&ph,     g_h);
    cudaGetSymbolAddress((void**)&pres1,  g_res1);
    cudaGetSymbolAddress((void**)&pxnh,   g_xnh);
    cudaGetSymbolAddress((void**)&pqkvh,  g_qkvh);
    cudaGetSymbolAddress((void**)&poh,    g_oh);
    cudaGetSymbolAddress((void**)&pffh,   g_ffh);
    cudaGetSymbolAddress((void**)&pwqkv,  g_wqkv);
    cudaGetSymbolAddress((void**)&pwcv,   g_wcv);
    cudaGetSymbolAddress((void**)&pw1,    g_w1);
    cudaGetSymbolAddress((void**)&pw2,    g_w2);

    cudaFuncSetAttribute(fused_attn_kernel,
                         cudaFuncAttributeMaxDynamicSharedMemorySize,
                         ATTN_SMEM);
    cudaFuncSetAttribute(hgemm_kernel<0, true>,
                         cudaFuncAttributeMaxDynamicSharedMemorySize, HG_SMEM);
    cudaFuncSetAttribute(hgemm_kernel<1, true>,
                         cudaFuncAttributeMaxDynamicSharedMemorySize, HG_SMEM);
    cudaFuncSetAttribute(hgemm_kernel<2, false>,
                         cudaFuncAttributeMaxDynamicSharedMemorySize, HG_SMEM);
    cudaFuncSetAttribute(hgemm_kernel<3, false>,
                         cudaFuncAttributeMaxDynamicSharedMemorySize, HG_SMEM);

    cudaMemcpyAsync(ph, x, sizeof(float) * (size_t)BS * EE,
                    cudaMemcpyDeviceToDevice);

    // ---- weight conversion pre-pass (vectorized) ----
    {
        long long nq8 = (3LL * LL * HH * EE * DHH) / 8;
        pack_qkv_kernel<<<(int)((nq8 + 255) / 256), 256>>>(Wq, Wk, Wv, pwqkv);
        int ncv8 = LL * EE * EE / 8;
        cvt_f2h_kernel<<<(ncv8 + 255) / 256, 256>>>(Wconv, pwcv, ncv8);
        int n18 = LL * EE * FF_ / 8;
        cvt_f2h_kernel<<<(n18 + 255) / 256, 256>>>(W1, pw1, n18);
        cvt_f2h_kernel<<<(n18 + 255) / 256, 256>>>(W2, pw2, n18);
    }

    const float inv_scale = 1.f / sqrtf((float)SS);
    const int MT = (BS + 127) / 128;  // 50 row tiles
    const int LNB = (BS + 7) / 8;     // warp-per-row LN blocks

    for (int l = 0; l < LL; l++) {
        const __half* wqkv_l = pwqkv + (long long)l * EE * NQKV;
        const __half* wcv_l  = pwcv + (long long)l * EE * EE;
        const __half* w1_l   = pw1 + (long long)l * EE * FF_;
        const __half* w2_l   = pw2 + (long long)l * FF_ * EE;
        const float* b1_l = b1 + (long long)l * FF_;
        const float* b2_l = b2 + (long long)l * EE;

        // LN1 -> half
        layernorm_kernel<<<LNB, 256>>>(ph, ln1_w + l * EE, ln1_b + l * EE,
                                       pxnh);

        // packed QKV: [6304 x 768] @ [768 x 2304] -> half
        {
            dim3 g(NQKV / 256, MT, 1);
            hgemm_kernel<0, true><<<g, 256, HG_SMEM>>>(
                pxnh, wqkv_l, pqkvh, nullptr, nullptr,
                BS, NQKV, EE, EE, NQKV, NQKV);
        }

        // fused attention: QK^T -> softmax -> PV, all in smem
        {
            dim3 g((SS + 63) / 64, BB * HH);
            fused_attn_kernel<<<g, 256, ATTN_SMEM>>>(pqkvh, poh, inv_scale);
        }

        // res1 = O @ Wconv + h   (fp32 out)
        {
            dim3 g(EE / 256, MT, 1);
            hgemm_kernel<2, false><<<g, 256, HG_SMEM>>>(
                poh, wcv_l, pres1, nullptr, ph,
                BS, EE, EE, EE, EE, EE);
        }

        // LN2 -> half
        layernorm_kernel<<<LNB, 256>>>(pres1, ln2_w + l * EE, ln2_b + l * EE,
                                       pxnh);

        // FF1 = gelu(xn2 @ W1 + b1) -> half
        {
            dim3 g(FF_ / 256, MT, 1);
            hgemm_kernel<1, true><<<g, 256, HG_SMEM>>>(
                pxnh, w1_l, pffh, b1_l, nullptr,
                BS, FF_, EE, EE, FF_, FF_);
        }

        // h = FF1 @ W2 + b2 + res1  (fp32 out)
        {
            dim3 g(EE / 256, MT, 1);
            hgemm_kernel<3, false><<<g, 256, HG_SMEM>>>(
                pffh, w2_l, ph, b2_l, pres1,
                BS, EE, FF_, FF_, EE, EE);
        }
    }

    // classifier + softmax
    classifier_kernel<<<BB, 256>>>(ph, Wc, bc, out);
}

// round 15
// speedup vs baseline: 1.2043x; 1.2043x over previous
#include <cuda_runtime.h>
#include <cuda_fp16.h>
#include <mma.h>
#include <math.h>
#include <stdint.h>

using namespace nvcuda;

// ---------------- problem constants ----------------
#define BB 32
#define SS 197
#define EE 768
#define HH 12
#define DHH 64
#define FF_ 2048
#define LL 4
#define CC 1000
#define BS (BB * SS)     // 6304
#define SP2 256          // padded key length inside fused attention
#define NQKV 2304        // 3 * H * DH packed output width
#define LN_EPS 1e-5f

// ---------------- scratch (device globals; allocation-free rule) ------------
__device__ float  g_h    [BS * EE];
__device__ float  g_res1 [BS * EE];
__device__ __half g_xnh  [BS * EE];
__device__ __half g_qkvh [(BS + 32) * NQKV];
__device__ __half g_oh   [BS * EE];
__device__ __half g_ffh  [BS * FF_];
// fp16 weights (converted once per launch)
__device__ __half g_wqkv [LL * EE * NQKV];
__device__ __half g_wcv  [LL * EE * EE];
__device__ __half g_w1   [LL * EE * FF_];
__device__ __half g_w2   [LL * FF_ * EE];

// ---------------- cp.async helpers ------------------------------------------
__device__ __forceinline__ void cp_async16(void* smem_dst, const void* gsrc,
                                           bool pred) {
    unsigned int s = (unsigned int)__cvta_generic_to_shared(smem_dst);
    int sz = pred ? 16 : 0;
    asm volatile("cp.async.cg.shared.global [%0], [%1], 16, %2;\n"
                 :: "r"(s), "l"(gsrc), "r"(sz));
}
__device__ __forceinline__ void cp_commit() {
    asm volatile("cp.async.commit_group;\n" ::: "memory");
}
template <int N>
__device__ __forceinline__ void cp_wait() {
    asm volatile("cp.async.wait_group %0;\n" :: "n"(N) : "memory");
}

// ---------------- weight conversion (vectorized: 8 elems/thread) ------------
__global__ void cvt_f2h_kernel(const float* __restrict__ src,
                               __half* __restrict__ dst, int n8) {
    int i = blockIdx.x * 256 + threadIdx.x;
    if (i >= n8) return;
    long long o = (long long)i * 8;
    float4 v0 = *reinterpret_cast<const float4*>(src + o);
    float4 v1 = *reinterpret_cast<const float4*>(src + o + 4);
    __half2 h[4];
    h[0] = __floats2half2_rn(v0.x, v0.y);
    h[1] = __floats2half2_rn(v0.z, v0.w);
    h[2] = __floats2half2_rn(v1.x, v1.y);
    h[3] = __floats2half2_rn(v1.z, v1.w);
    *reinterpret_cast<uint4*>(dst + o) = *reinterpret_cast<uint4*>(h);
}

__global__ void pack_qkv_kernel(const float* __restrict__ Wq,
                                const float* __restrict__ Wk,
                                const float* __restrict__ Wv,
                                __half* __restrict__ dst) {
    const long long per = (long long)LL * HH * EE * DHH;   // 2359296
    long long i8 = ((long long)blockIdx.x * 256 + threadIdx.x) * 8;
    if (i8 >= 3 * per) return;
    int mat = (int)(i8 / per);
    long long r = i8 % per;
    int d = (int)(r % DHH);                  // multiple of 8
    int e = (int)((r / DHH) % EE);
    int h = (int)((r / (DHH * EE)) % HH);
    int l = (int)(r / ((long long)DHH * EE * HH));
    const float* src = (mat == 0) ? Wq : (mat == 1) ? Wk : Wv;
    float4 v0 = *reinterpret_cast<const float4*>(src + r);
    float4 v1 = *reinterpret_cast<const float4*>(src + r + 4);
    __half2 hh[4];
    hh[0] = __floats2half2_rn(v0.x, v0.y);
    hh[1] = __floats2half2_rn(v0.z, v0.w);
    hh[2] = __floats2half2_rn(v1.x, v1.y);
    hh[3] = __floats2half2_rn(v1.z, v1.w);
    *reinterpret_cast<uint4*>(
        dst + ((long long)l * EE + e) * NQKV + mat * 768 + h * 64 + d) =
        *reinterpret_cast<uint4*>(hh);
}

// ---------------- layernorm: warp per row (shuffle-only, vectorized) --------
__global__ __launch_bounds__(256)
void layernorm_kernel(const float* __restrict__ x,
                      const float* __restrict__ w,
                      const float* __restrict__ b,
                      __half* __restrict__ out) {
    int wid = threadIdx.x >> 5, lane = threadIdx.x & 31;
    int row = blockIdx.x * 8 + wid;
    if (row >= BS) return;
    const float4* xr4 = reinterpret_cast<const float4*>(
        x + (long long)row * EE);
    const float4* w4 = reinterpret_cast<const float4*>(w);
    const float4* b4 = reinterpret_cast<const float4*>(b);
    __half* orow = out + (long long)row * EE;

    float4 v[6];
    float s = 0.f, s2 = 0.f;
    #pragma unroll
    for (int j = 0; j < 6; j++) {
        v[j] = xr4[lane + j * 32];
        s  += v[j].x + v[j].y + v[j].z + v[j].w;
        s2 += v[j].x * v[j].x + v[j].y * v[j].y
            + v[j].z * v[j].z + v[j].w * v[j].w;
    }
    #pragma unroll
    for (int off = 16; off > 0; off >>= 1) {
        s  += __shfl_xor_sync(0xffffffffu, s, off);
        s2 += __shfl_xor_sync(0xffffffffu, s2, off);
    }
    float mu = s * (1.f / EE);
    float var = s2 * (1.f / EE) - mu * mu;
    float rstd = rsqrtf(var + LN_EPS);
    #pragma unroll
    for (int j = 0; j < 6; j++) {
        float4 wv = w4[lane + j * 32];
        float4 bv = b4[lane + j * 32];
        __half2 h0 = __floats2half2_rn((v[j].x - mu) * rstd * wv.x + bv.x,
                                       (v[j].y - mu) * rstd * wv.y + bv.y);
        __half2 h1 = __floats2half2_rn((v[j].z - mu) * rstd * wv.z + bv.z,
                                       (v[j].w - mu) * rstd * wv.w + bv.w);
        uint2 pk;
        pk.x = *reinterpret_cast<unsigned int*>(&h0);
        pk.y = *reinterpret_cast<unsigned int*>(&h1);
        *reinterpret_cast<uint2*>(orow + (lane + j * 32) * 4) = pk;
    }
}

// ---------------- fused flash attention -------------------------------------
// One block per (q-tile of 64, b*h). All intermediates in smem.
#define LDQ 72
#define LDK 72
#define LDP 264
#define LDSF 260
#define LDV 72
#define LDSO 68
#define SM_Q 0
#define SM_K 9216                      // 64*LDQ*2
#define SM_SF (SM_K + SP2 * LDK * 2)   // 46080
#define SM_OS (SM_SF + 40960)
#define ATTN_SMEM (SM_SF + 64 * LDSF * 4)   // 112640 B

__global__ __launch_bounds__(256)
void fused_attn_kernel(const __half* __restrict__ qkv,
                       __half* __restrict__ o, float inv_scale) {
    extern __shared__ char sm[];
    __half* Qs = reinterpret_cast<__half*>(sm + SM_Q);
    __half* Ks = reinterpret_cast<__half*>(sm + SM_K);
    __half* Ph = Ks;
    float*  Sf = reinterpret_cast<float*>(sm + SM_SF);
    __half* Vs = reinterpret_cast<__half*>(sm + SM_SF);
    float*  Os = reinterpret_cast<float*>(sm + SM_OS);

    int qt = blockIdx.x;
    int bh = blockIdx.y;
    int b = bh / HH, h = bh % HH;
    const __half* base = qkv + (long long)b * SS * NQKV + h * 64;
    int q0 = qt * 64;

    int tid = threadIdx.x;
    int wid = tid >> 5, lane = tid & 31;
    const uint4 z4 = {0u, 0u, 0u, 0u};

    #pragma unroll
    for (int e = 0; e < 2; e++) {
        int i = tid + e * 256;
        int r = i >> 3, c = (i & 7) * 8;
        int gq = q0 + r;
        uint4 v = (gq < SS)
            ? *reinterpret_cast<const uint4*>(base + (long long)gq * NQKV + c)
            : z4;
        *reinterpret_cast<uint4*>(&Qs[r * LDQ + c]) = v;
    }
    #pragma unroll
    for (int e = 0; e < 8; e++) {
        int i = tid + e * 256;
        int r = i >> 3, c = (i & 7) * 8;
        uint4 v = (r < SS)
            ? *reinterpret_cast<const uint4*>(base + 768 +
                                              (long long)r * NQKV + c)
            : z4;
        *reinterpret_cast<uint4*>(&Ks[r * LDK + c]) = v;
    }
    __syncthreads();

    {
        wmma::fragment<wmma::accumulator, 16, 16, 16, float> acc[4][2];
        #pragma unroll
        for (int i = 0; i < 4; i++)
            #pragma unroll
            for (int j = 0; j < 2; j++)
                wmma::fill_fragment(acc[i][j], 0.f);
        #pragma unroll
        for (int kt = 0; kt < 4; kt++) {
            wmma::fragment<wmma::matrix_a, 16, 16, 16, __half,
                           wmma::row_major> af[4];
            wmma::fragment<wmma::matrix_b, 16, 16, 16, __half,
                           wmma::col_major> bf[2];
            #pragma unroll
            for (int i = 0; i < 4; i++)
                wmma::load_matrix_sync(af[i],
                    Qs + (i * 16) * LDQ + kt * 16, LDQ);
            #pragma unroll
            for (int j = 0; j < 2; j++)
                wmma::load_matrix_sync(bf[j],
                    Ks + (wid * 32 + j * 16) * LDK + kt * 16, LDK);
            #pragma unroll
            for (int i = 0; i < 4; i++)
                #pragma unroll
                for (int j = 0; j < 2; j++)
                    wmma::mma_sync(acc[i][j], af[i], bf[j], acc[i][j]);
        }
        #pragma unroll
        for (int i = 0; i < 4; i++)
            #pragma unroll
            for (int j = 0; j < 2; j++)
                wmma::store_matrix_sync(
                    Sf + (i * 16) * LDSF + wid * 32 + j * 16, acc[i][j],
                    LDSF, wmma::mem_row_major);
    }
    __syncthreads();

    #pragma unroll
    for (int rr = 0; rr < 8; rr++) {
        int r = wid * 8 + rr;
        float m = -1e30f;
        for (int c = lane; c < SS; c += 32)
            m = fmaxf(m, Sf[r * LDSF + c] * inv_scale);
        #pragma unroll
        for (int off = 16; off > 0; off >>= 1)
            m = fmaxf(m, __shfl_xor_sync(0xffffffffu, m, off));
        float sum = 0.f;
        for (int c = lane; c < SS; c += 32) {
            float e = expf(Sf[r * LDSF + c] * inv_scale - m);
            Sf[r * LDSF + c] = e;
            sum += e;
        }
        #pragma unroll
        for (int off = 16; off > 0; off >>= 1)
            sum += __shfl_xor_sync(0xffffffffu, sum, off);
        float inv = 1.f / sum;
        for (int c = lane; c < SP2; c += 32)
            Ph[r * LDP + c] = (c < SS)
                ? __float2half_rn(Sf[r * LDSF + c] * inv) : __half(0.f);
    }
    __syncthreads();

    #pragma unroll
    for (int e = 0; e < 8; e++) {
        int i = tid + e * 256;
        int r = i >> 3, c = (i & 7) * 8;
        uint4 v = (r < SS)
            ? *reinterpret_cast<const uint4*>(base + 1536 +
                                              (long long)r * NQKV + c)
            : z4;
        *reinterpret_cast<uint4*>(&Vs[r * LDV + c]) = v;
    }
    __syncthreads();

    {
        int wm = wid >> 1, wn = wid & 1;
        wmma::fragment<wmma::accumulator, 16, 16, 16, float> acc[2];
        wmma::fill_fragment(acc[0], 0.f);
        wmma::fill_fragment(acc[1], 0.f);
        #pragma unroll
        for (int kt = 0; kt < SP2 / 16; kt++) {
            wmma::fragment<wmma::matrix_a, 16, 16, 16, __half,
                           wmma::row_major> af;
            wmma::fragment<wmma::matrix_b, 16, 16, 16, __half,
                           wmma::row_major> bf[2];
            wmma::load_matrix_sync(af, Ph + (wm * 16) * LDP + kt * 16, LDP);
            #pragma unroll
            for (int j = 0; j < 2; j++)
                wmma::load_matrix_sync(bf[j],
                    Vs + (kt * 16) * LDV + wn * 32 + j * 16, LDV);
            #pragma unroll
            for (int j = 0; j < 2; j++)
                wmma::mma_sync(acc[j], af, bf[j], acc[j]);
        }
        #pragma unroll
        for (int j = 0; j < 2; j++)
            wmma::store_matrix_sync(
                Os + (wm * 16) * LDSO + wn * 32 + j * 16, acc[j],
                LDSO, wmma::mem_row_major);
    }
    __syncthreads();

    #pragma unroll
    for (int e = 0; e < 16; e++) {
        int i = tid + e * 256;
        int m = i >> 6, d = i & 63;
        int gq = q0 + m;
        if (gq < SS)
            o[((long long)b * SS + gq) * EE + h * 64 + d] =
                __float2half_rn(Os[m * LDSO + d]);
    }
}

// ---------------- FP16 TC GEMM: 128x128 tile, BK=64, cp.async 3-stage -------
// Requires: K % 64 == 0, N % 128 == 0, 16B-aligned rows (lda/ldb % 8 == 0).
// Only M may be ragged. 3-stage pipeline; barriers at half the BK=32 rate,
// 32 HMMA per warp between barriers. Smem 107.5 KB -> still 2 CTAs/SM.
// EPI: 0: C=acc  1: C=gelu(acc+bias)  2: C=acc+D  3: C=acc+bias+D
#define HG_LDA 72
#define HG_LDB 136
#define HG_STAGE_HALFS (128 * HG_LDA + 64 * HG_LDB)   // 17920
#define HG_SMEM (3 * HG_STAGE_HALFS * 2)              // 107520 (> epi 34816)

template <int EPI, bool OUTH>
__global__ __launch_bounds__(256)
void hgemm_kernel(const __half* __restrict__ A, const __half* __restrict__ Bm,
                  void* __restrict__ Cv,
                  const float* __restrict__ bias, const float* __restrict__ Dm,
                  int M, int N, int K, int lda, int ldb, int ldc) {
    constexpr int BM = 128, BK = 64;
    constexpr int WARP_M = 64, WARP_N = 32;
    constexpr int AF = 4, BF = 2;
    constexpr int LDA_H = HG_LDA;
    constexpr int LDB_H = HG_LDB;
    constexpr int LDST = 68;

    const int m0 = blockIdx.y * BM, n0 = blockIdx.x * 128;

    extern __shared__ __align__(16) char smem_raw[];
    float* epi = reinterpret_cast<float*>(smem_raw);

    int tid = threadIdx.x;
    int wid = tid >> 5;
    int wm = wid & 1, wn = wid >> 1;   // 2 x 4 warp grid (64m x 32n tiles)

    wmma::fragment<wmma::accumulator, 16, 16, 16, float> acc[AF][BF];
    #pragma unroll
    for (int i = 0; i < AF; i++)
        #pragma unroll
        for (int j = 0; j < BF; j++)
            wmma::fill_fragment(acc[i][j], 0.f);

    // per-thread copy coordinates
    // A: 128 x 64 halfs = 1024 vec16 -> 4/thread; row = tid>>3, col = (tid&7)*8
    // B: 64 x 128 halfs = 1024 vec16 -> 4/thread; row = tid>>4, col = (tid&15)*8
    const int ar = tid >> 3, ac = (tid & 7) * 8;   // e adds 32 rows
    const int br = tid >> 4, bc = (tid & 15) * 8;  // e adds 16 rows
    bool apred[4];
    long long arow[4];
    #pragma unroll
    for (int e = 0; e < 4; e++) {
        int m = ar + e * 32;
        apred[e] = (m0 + m < M);
        arow[e] = (long long)(apred[e] ? (m0 + m) : (M - 1)) * lda;
    }

    auto loadStage = [&](int t, int s) {
        __half* As = reinterpret_cast<__half*>(smem_raw) + s * HG_STAGE_HALFS;
        __half* Bs = As + BM * LDA_H;
        int k0 = t * BK;
        #pragma unroll
        for (int e = 0; e < 4; e++)
            cp_async16(&As[(ar + e * 32) * LDA_H + ac],
                       A + arow[e] + k0 + ac, apred[e]);
        #pragma unroll
        for (int e = 0; e < 4; e++)
            cp_async16(&Bs[(br + e * 16) * LDB_H + bc],
                       Bm + (long long)(k0 + br + e * 16) * ldb + n0 + bc,
                       true);
        cp_commit();
    };

    auto compute = [&](int s) {
        const __half* As = reinterpret_cast<const __half*>(smem_raw)
                           + s * HG_STAGE_HALFS;
        const __half* Bs = As + BM * LDA_H;
        #pragma unroll
        for (int kt = 0; kt < BK / 16; kt++) {
            wmma::fragment<wmma::matrix_a, 16, 16, 16, __half,
                           wmma::row_major> af[AF];
            wmma::fragment<wmma::matrix_b, 16, 16, 16, __half,
                           wmma::row_major> bf[BF];
            #pragma unroll
            for (int i = 0; i < AF; i++)
                wmma::load_matrix_sync(
                    af[i], As + (wm * WARP_M + i * 16) * LDA_H + kt * 16,
                    LDA_H);
            #pragma unroll
            for (int j = 0; j < BF; j++)
                wmma::load_matrix_sync(
                    bf[j], Bs + (kt * 16) * LDB_H + wn * WARP_N + j * 16,
                    LDB_H);
            #pragma unroll
            for (int i = 0; i < AF; i++)
                #pragma unroll
                for (int j = 0; j < BF; j++)
                    wmma::mma_sync(acc[i][j], af[i], bf[j], acc[i][j]);
        }
    };

    // ---- 3-stage cp.async pipeline, one barrier per iter ----
    const int nk = K / BK;
    loadStage(0, 0);
    if (nk > 1) loadStage(1, 1);
    for (int t = 0; t < nk; t++) {
        if (t + 1 < nk) cp_wait<1>(); else cp_wait<0>();
        __syncthreads();
        if (t + 2 < nk) loadStage(t + 2, (t + 2) % 3);
        compute(t % 3);
    }
    __syncthreads();

    // ---- epilogue: two 64-wide column halves staged through fp32 smem ----
    #pragma unroll
    for (int h = 0; h < 2; h++) {
        if ((wn >> 1) == h) {
            int cbase = (wn & 1) * 32;
            #pragma unroll
            for (int i = 0; i < AF; i++)
                #pragma unroll
                for (int j = 0; j < BF; j++)
                    wmma::store_matrix_sync(
                        epi + (wm * WARP_M + i * 16) * LDST + cbase + j * 16,
                        acc[i][j], LDST, wmma::mem_row_major);
        }
        __syncthreads();

        int nl = tid & 63;
        int n = n0 + h * 64 + nl;
        {
            float bn_ = (EPI == 1 || EPI == 3) ? bias[n] : 0.f;
            #pragma unroll 8
            for (int p = 0; p < 32; p++) {
                int r = (tid >> 6) + p * 4;
                int m = m0 + r;
                if (m >= M) break;
                float v = epi[r * LDST + nl];
                if (EPI == 1) {
                    v += bn_;
                    v = 0.5f * v * (1.f + erff(v * 0.70710678118654752f));
                } else if (EPI == 2) {
                    v += Dm[(long long)m * ldc + n];
                } else if (EPI == 3) {
                    v += bn_ + Dm[(long long)m * ldc + n];
                }
                if (OUTH)
                    ((__half*)Cv)[(long long)m * ldc + n] = __float2half_rn(v);
                else
                    ((float*)Cv)[(long long)m * ldc + n] = v;
            }
        }
        if (h == 0) __syncthreads();
    }
}

// ---------------- classifier + final softmax: one block per batch ------------
__global__ void classifier_kernel(const float* __restrict__ hbuf,
                                  const float* __restrict__ Wc,
                                  const float* __restrict__ bc,
                                  float* __restrict__ out) {
    int b = blockIdx.x;
    int tid = threadIdx.x;  // 256
    __shared__ float xs[EE];
    __shared__ float lg[CC];
    __shared__ float red[256];

    const float* xr = hbuf + (long long)b * SS * EE;  // row s=0
    for (int i = tid; i < EE; i += 256) xs[i] = xr[i];
    __syncthreads();

    for (int c = tid; c < CC; c += 256) {
        float acc = bc[c];
        for (int e = 0; e < EE; e++) acc += xs[e] * Wc[(long long)e * CC + c];
        lg[c] = acc;
    }
    __syncthreads();

    float m = -1e30f;
    for (int c = tid; c < CC; c += 256) m = fmaxf(m, lg[c]);
    red[tid] = m; __syncthreads();
    for (int st = 128; st > 0; st >>= 1) {
        if (tid < st) red[tid] = fmaxf(red[tid], red[tid + st]);
        __syncthreads();
    }
    m = red[0];
    __syncthreads();

    float sum = 0.f;
    for (int c = tid; c < CC; c += 256) {
        float e = expf(lg[c] - m);
        lg[c] = e; sum += e;
    }
    red[tid] = sum; __syncthreads();
    for (int st = 128; st > 0; st >>= 1) {
        if (tid < st) red[tid] += red[tid + st];
        __syncthreads();
    }
    float inv = 1.f / red[0];
    for (int c = tid; c < CC; c += 256)
        out[(long long)b * CC + c] = lg[c] * inv;
}

// ---------------- host orchestration ----------------------------------------
extern "C" void kernel_launch(void* const* d_in, const int* in_sizes, int n_in,
                              void* d_out, int out_size) {
    const float* x     = (const float*)d_in[0];
    const float* Wk    = (const float*)d_in[1];
    const float* Wq    = (const float*)d_in[2];
    const float* Wv    = (const float*)d_in[3];
    const float* Wconv = (const float*)d_in[4];
    const float* ln1_w = (const float*)d_in[5];
    const float* ln1_b = (const float*)d_in[6];
    const float* ln2_w = (const float*)d_in[7];
    const float* ln2_b = (const float*)d_in[8];
    const float* W1    = (const float*)d_in[9];
    const float* b1    = (const float*)d_in[10];
    const float* W2    = (const float*)d_in[11];
    const float* b2    = (const float*)d_in[12];
    const float* Wc    = (const float*)d_in[13];
    const float* bc    = (const float*)d_in[14];
    float* out = (float*)d_out;

    float *ph, *pres1;
    __half *pxnh, *pqkvh, *poh, *pffh, *pwqkv, *pwcv, *pw1, *pw2;
    cudaGetSymbolAddress((void**)&ph,     g_h);
    cudaGetSymbolAddress((void**)&pres1,  g_res1);
    cudaGetSymbolAddress((void**)&pxnh,   g_xnh);
    cudaGetSymbolAddress((void**)&pqkvh,  g_qkvh);
    cudaGetSymbolAddress((void**)&poh,    g_oh);
    cudaGetSymbolAddress((void**)&pffh,   g_ffh);
    cudaGetSymbolAddress((void**)&pwqkv,  g_wqkv);
    cudaGetSymbolAddress((void**)&pwcv,   g_wcv);
    cudaGetSymbolAddress((void**)&pw1,    g_w1);
    cudaGetSymbolAddress((void**)&pw2,    g_w2);

    cudaFuncSetAttribute(fused_attn_kernel,
                         cudaFuncAttributeMaxDynamicSharedMemorySize,
                         ATTN_SMEM);
    cudaFuncSetAttribute(hgemm_kernel<0, true>,
                         cudaFuncAttributeMaxDynamicSharedMemorySize, HG_SMEM);
    cudaFuncSetAttribute(hgemm_kernel<1, true>,
                         cudaFuncAttributeMaxDynamicSharedMemorySize, HG_SMEM);
    cudaFuncSetAttribute(hgemm_kernel<2, false>,
                         cudaFuncAttributeMaxDynamicSharedMemorySize, HG_SMEM);
    cudaFuncSetAttribute(hgemm_kernel<3, false>,
                         cudaFuncAttributeMaxDynamicSharedMemorySize, HG_SMEM);

    cudaMemcpyAsync(ph, x, sizeof(float) * (size_t)BS * EE,
                    cudaMemcpyDeviceToDevice);

    // ---- weight conversion pre-pass (vectorized) ----
    {
        long long nq8 = (3LL * LL * HH * EE * DHH) / 8;
        pack_qkv_kernel<<<(int)((nq8 + 255) / 256), 256>>>(Wq, Wk, Wv, pwqkv);
        int ncv8 = LL * EE * EE / 8;
        cvt_f2h_kernel<<<(ncv8 + 255) / 256, 256>>>(Wconv, pwcv, ncv8);
        int n18 = LL * EE * FF_ / 8;
        cvt_f2h_kernel<<<(n18 + 255) / 256, 256>>>(W1, pw1, n18);
        cvt_f2h_kernel<<<(n18 + 255) / 256, 256>>>(W2, pw2, n18);
    }

    const float inv_scale = 1.f / sqrtf((float)SS);
    const int MT = (BS + 127) / 128;  // 50 row tiles
    const int LNB = (BS + 7) / 8;     // warp-per-row LN blocks

    for (int l = 0; l < LL; l++) {
        const __half* wqkv_l = pwqkv + (long long)l * EE * NQKV;
        const __half* wcv_l  = pwcv + (long long)l * EE * EE;
        const __half* w1_l   = pw1 + (long long)l * EE * FF_;
        const __half* w2_l   = pw2 + (long long)l * FF_ * EE;
        const float* b1_l = b1 + (long long)l * FF_;
        const float* b2_l = b2 + (long long)l * EE;

        // LN1 -> half
        layernorm_kernel<<<LNB, 256>>>(ph, ln1_w + l * EE, ln1_b + l * EE,
                                       pxnh);

        // packed QKV: [6304 x 768] @ [768 x 2304] -> half
        {
            dim3 g(NQKV / 128, MT, 1);
            hgemm_kernel<0, true><<<g, 256, HG_SMEM>>>(
                pxnh, wqkv_l, pqkvh, nullptr, nullptr,
                BS, NQKV, EE, EE, NQKV, NQKV);
        }

        // fused attention: QK^T -> softmax -> PV, all in smem
        {
            dim3 g((SS + 63) / 64, BB * HH);
            fused_attn_kernel<<<g, 256, ATTN_SMEM>>>(pqkvh, poh, inv_scale);
        }

        // res1 = O @ Wconv + h   (fp32 out)
        {
            dim3 g(EE / 128, MT, 1);
            hgemm_kernel<2, false><<<g, 256, HG_SMEM>>>(
                poh, wcv_l, pres1, nullptr, ph,
                BS, EE, EE, EE, EE, EE);
        }

        // LN2 -> half
        layernorm_kernel<<<LNB, 256>>>(pres1, ln2_w + l * EE, ln2_b + l * EE,
                                       pxnh);

        // FF1 = gelu(xn2 @ W1 + b1) -> half
        {
            dim3 g(FF_ / 128, MT, 1);
            hgemm_kernel<1, true><<<g, 256, HG_SMEM>>>(
                pxnh, w1_l, pffh, b1_l, nullptr,
                BS, FF_, EE, EE, FF_, FF_);
        }

        // h = FF1 @ W2 + b2 + res1  (fp32 out)
        {
            dim3 g(EE / 128, MT, 1);
            hgemm_kernel<3, false><<<g, 256, HG_SMEM>>>(
                pffh, w2_l, ph, b2_l, pres1,
                BS, EE, FF_, FF_, EE, EE);
        }
    }

    // classifier + softmax
    classifier_kernel<<<BB, 256>>>(ph, Wc, bc, out);
}